// round 15
// baseline (speedup 1.0000x reference)
#include <cuda_runtime.h>
#include <math.h>

#define LVL 4
#define BAT 128
#define INW 512
#define CTXW 512
#define STW 512
#define RW 256
#define CW 256
#define DW 1536
#define KC 32
#define KHALF 768                     /* K per gate split-K block */
#define NCH_GATE (KHALF/KC)           /* 24 chunks */
#define NCH_UV 16                     /* 512 K per uv segment */
#define H_SIZE (LVL*BAT*STW)          /* 262144 */
#define H_SIZE4 (H_SIZE/4)            /* 65536 */
#define M_LVL_STRIDE (BAT*RW*CW)      /* 8388608 */

/* combined kernel dynamic smem: 3 stages x (A 64x36 + 3x B 32x36) floats */
#define GATE_SMEM_BYTES  (3 * (64 * 36 + 3 * 32 * 36) * 4)   /* 69120 */
/* uv_h kernel dynamic smem: 3 stages x (A 64x36 + 2x B 32x36) floats */
#define UV_SMEM_BYTES    (3 * (64 * 36 + 2 * 32 * 36) * 4)   /* 55296 */

// scratch (allocation-free rule: __device__ globals)
__device__ __align__(16) float g_gate_p[2][3][LVL][BAT][STW];  // gate split-K partials (6 MB)
__device__ __align__(16) float g_uv_p[3][2][LVL][BAT][RW];     // u/v 3-segment partials (3 MB)

__device__ __forceinline__ float sigmoidf_(float x) { return 1.0f / (1.0f + __expf(-x)); }

__device__ __forceinline__ void mma_tf32(float* d, unsigned a0, unsigned a1,
                                         unsigned a2, unsigned a3,
                                         unsigned b0, unsigned b1)
{
    asm volatile(
        "mma.sync.aligned.m16n8k8.row.col.f32.tf32.tf32.f32 "
        "{%0,%1,%2,%3}, {%4,%5,%6,%7}, {%8,%9}, {%0,%1,%2,%3};\n"
        : "+f"(d[0]), "+f"(d[1]), "+f"(d[2]), "+f"(d[3])
        : "r"(a0), "r"(a1), "r"(a2), "r"(a3), "r"(b0), "r"(b1));
}

__device__ __forceinline__ void cp16(void* dst, const void* src) {
    unsigned ds = (unsigned)__cvta_generic_to_shared(dst);
    asm volatile("cp.async.ca.shared.global [%0], [%1], 16;" :: "r"(ds), "l"(src));
}
__device__ __forceinline__ void cp_commit() { asm volatile("cp.async.commit_group;"); }
template<int N> __device__ __forceinline__ void cp_wait() {
    asm volatile("cp.async.wait_group %0;" :: "n"(N));
}

// ---------------------------------------------------------------------------
// COMBINED launch: gate GEMM blocks + uv_xc GEMM blocks in one grid.
//   blockIdx.x <  16 : gate role  (otile=x)      — 3 gates share A; split-K x2
//   blockIdx.x >= 16 : uv_xc role (otile=x-16)   — u+v share A; K segment
//                      [512+seg*512, 1024+seg*512) of wv = x|c (NO h_new dep,
//                      so it runs concurrently with the gates)
// Both roles: tile M=64 x N=32(/matrix), 128 threads (2x2 warps, 32x16 warp
// tile), 3-stage cp.async pipeline (wait<1> needs >=2 pending groups — hence
// wait<0> on the final iteration; R6-class bug otherwise), truncation-mode
// tf32, stride-36 conflict-free smem rows.
// grid: (x=24, y=mtile*2+seg=4, z=l=4) = 384 blocks.
// ---------------------------------------------------------------------------
__global__ __launch_bounds__(128)
void gate_uvxc_gemm(const float* __restrict__ x, const float* __restrict__ c,
                    const float* __restrict__ h,
                    const float* __restrict__ phi_w, const float* __restrict__ alpha_w,
                    const float* __restrict__ beta_w,
                    const float* __restrict__ u_w, const float* __restrict__ v_w)
{
    extern __shared__ float smem_dyn[];
    const int l     = blockIdx.z;
    const int mtile = blockIdx.y >> 1;
    const int seg   = blockIdx.y & 1;

    const int t = threadIdx.x;
    const int w = t >> 5, lane = t & 31;
    const int wm = w >> 1, wn = w & 1;
    const int g = lane >> 2, tg = lane & 3;

    if (blockIdx.x < 16) {
        // ------------------------- GATE ROLE --------------------------------
        float (*As)[64][36]    = (float(*)[64][36])smem_dyn;
        float (*Bs)[3][32][36] = (float(*)[3][32][36])(smem_dyn + 3 * 64 * 36);
        const int otile = blockIdx.x;
        const int kbase = seg * KHALF;

        const float* Wg[3] = { phi_w   + (size_t)l * STW * DW,
                               alpha_w + (size_t)l * STW * DW,
                               beta_w  + (size_t)l * STW * DW };

        float acc[3][2][2][4];
        #pragma unroll
        for (int ga = 0; ga < 3; ga++)
            #pragma unroll
            for (int mi = 0; mi < 2; mi++)
                #pragma unroll
                for (int ni = 0; ni < 2; ni++)
                    #pragma unroll
                    for (int r = 0; r < 4; r++) acc[ga][mi][ni][r] = 0.0f;

        auto load_chunk = [&](int kt, int s) {
            #pragma unroll
            for (int i = 0; i < 4; i++) {
                const int idx = i * 128 + t;
                const int row = idx >> 3, ch = idx & 7;
                const int k = kt + ch * 4;
                const int b = mtile * 64 + row;
                const float* src;
                if (k < INW)              src = x + (size_t)b * INW + k;
                else if (k < INW + CTXW)  src = c + (size_t)b * CTXW + (k - INW);
                else                      src = h + ((size_t)l * BAT + b) * STW + (k - INW - CTXW);
                cp16(&As[s][row][ch * 4], src);
            }
            #pragma unroll
            for (int i = 0; i < 6; i++) {
                const int idx = i * 128 + t;
                const int ga  = idx >> 8;
                const int rem = idx & 255;
                const int row = rem >> 3, ch = rem & 7;
                cp16(&Bs[s][ga][row][ch * 4],
                     Wg[ga] + (size_t)(otile * 32 + row) * DW + kt + ch * 4);
            }
            cp_commit();
        };

        load_chunk(kbase, 0);
        load_chunk(kbase + KC, 1);
        for (int it = 0; it < NCH_GATE; ++it) {
            const int s = it % 3;
            if (it + 1 < NCH_GATE) cp_wait<1>(); else cp_wait<0>();
            __syncthreads();
            if (it + 2 < NCH_GATE) load_chunk(kbase + (it + 2) * KC, (it + 2) % 3);

            #pragma unroll
            for (int ks = 0; ks < 4; ks++) {
                const int k0 = ks * 8;
                unsigned a[2][4];
                #pragma unroll
                for (int mi = 0; mi < 2; mi++) {
                    const int r0 = wm * 32 + mi * 16;
                    a[mi][0] = __float_as_uint(As[s][r0 + g][k0 + tg]);
                    a[mi][1] = __float_as_uint(As[s][r0 + g + 8][k0 + tg]);
                    a[mi][2] = __float_as_uint(As[s][r0 + g][k0 + tg + 4]);
                    a[mi][3] = __float_as_uint(As[s][r0 + g + 8][k0 + tg + 4]);
                }
                #pragma unroll
                for (int ga = 0; ga < 3; ga++) {
                    unsigned bb[2][2];
                    #pragma unroll
                    for (int ni = 0; ni < 2; ni++) {
                        const int n0 = wn * 16 + ni * 8 + g;
                        bb[ni][0] = __float_as_uint(Bs[s][ga][n0][k0 + tg]);
                        bb[ni][1] = __float_as_uint(Bs[s][ga][n0][k0 + tg + 4]);
                    }
                    #pragma unroll
                    for (int mi = 0; mi < 2; mi++)
                        #pragma unroll
                        for (int ni = 0; ni < 2; ni++)
                            mma_tf32(acc[ga][mi][ni], a[mi][0], a[mi][1], a[mi][2],
                                     a[mi][3], bb[ni][0], bb[ni][1]);
                }
            }
        }

        #pragma unroll
        for (int ga = 0; ga < 3; ga++)
            #pragma unroll
            for (int mi = 0; mi < 2; mi++) {
                const int r0 = mtile * 64 + wm * 32 + mi * 16;
                #pragma unroll
                for (int ni = 0; ni < 2; ni++) {
                    const int o0 = otile * 32 + wn * 16 + ni * 8 + tg * 2;
                    float2 v0 = { acc[ga][mi][ni][0], acc[ga][mi][ni][1] };
                    float2 v1 = { acc[ga][mi][ni][2], acc[ga][mi][ni][3] };
                    *(float2*)&g_gate_p[seg][ga][l][r0 + g][o0]     = v0;
                    *(float2*)&g_gate_p[seg][ga][l][r0 + g + 8][o0] = v1;
                }
            }
    } else {
        // ------------------------ UV_XC ROLE --------------------------------
        // K in wv coords: [512+seg*512, 1024+seg*512)  (x segment or c segment)
        float (*As)[64][36]    = (float(*)[64][36])smem_dyn;
        float (*Bs)[2][32][36] = (float(*)[2][32][36])(smem_dyn + 3 * 64 * 36);
        const int otile = blockIdx.x - 16;
        const int kbase = STW + seg * 512;

        const float* Wuv[2] = { u_w + (size_t)l * RW * DW,
                                v_w + (size_t)l * RW * DW };

        float acc[2][2][2][4];
        #pragma unroll
        for (int wv = 0; wv < 2; wv++)
            #pragma unroll
            for (int mi = 0; mi < 2; mi++)
                #pragma unroll
                for (int ni = 0; ni < 2; ni++)
                    #pragma unroll
                    for (int r = 0; r < 4; r++) acc[wv][mi][ni][r] = 0.0f;

        auto load_chunk = [&](int kt, int s) {
            #pragma unroll
            for (int i = 0; i < 4; i++) {
                const int idx = i * 128 + t;
                const int row = idx >> 3, ch = idx & 7;
                const int k = kt + ch * 4;          // in [512, 1536)
                const int b = mtile * 64 + row;
                const float* src = (k < STW + INW)
                    ? x + (size_t)b * INW + (k - STW)
                    : c + (size_t)b * CTXW + (k - STW - INW);
                cp16(&As[s][row][ch * 4], src);
            }
            #pragma unroll
            for (int i = 0; i < 4; i++) {
                const int idx = i * 128 + t;
                const int wv  = idx >> 8;
                const int rem = idx & 255;
                const int row = rem >> 3, ch = rem & 7;
                cp16(&Bs[s][wv][row][ch * 4],
                     Wuv[wv] + (size_t)(otile * 32 + row) * DW + kt + ch * 4);
            }
            cp_commit();
        };

        load_chunk(kbase, 0);
        load_chunk(kbase + KC, 1);
        for (int it = 0; it < NCH_UV; ++it) {
            const int s = it % 3;
            if (it + 1 < NCH_UV) cp_wait<1>(); else cp_wait<0>();
            __syncthreads();
            if (it + 2 < NCH_UV) load_chunk(kbase + (it + 2) * KC, (it + 2) % 3);

            #pragma unroll
            for (int ks = 0; ks < 4; ks++) {
                const int k0 = ks * 8;
                unsigned a[2][4];
                #pragma unroll
                for (int mi = 0; mi < 2; mi++) {
                    const int r0 = wm * 32 + mi * 16;
                    a[mi][0] = __float_as_uint(As[s][r0 + g][k0 + tg]);
                    a[mi][1] = __float_as_uint(As[s][r0 + g + 8][k0 + tg]);
                    a[mi][2] = __float_as_uint(As[s][r0 + g][k0 + tg + 4]);
                    a[mi][3] = __float_as_uint(As[s][r0 + g + 8][k0 + tg + 4]);
                }
                #pragma unroll
                for (int wv = 0; wv < 2; wv++) {
                    unsigned bb[2][2];
                    #pragma unroll
                    for (int ni = 0; ni < 2; ni++) {
                        const int n0 = wn * 16 + ni * 8 + g;
                        bb[ni][0] = __float_as_uint(Bs[s][wv][n0][k0 + tg]);
                        bb[ni][1] = __float_as_uint(Bs[s][wv][n0][k0 + tg + 4]);
                    }
                    #pragma unroll
                    for (int mi = 0; mi < 2; mi++)
                        #pragma unroll
                        for (int ni = 0; ni < 2; ni++)
                            mma_tf32(acc[wv][mi][ni], a[mi][0], a[mi][1], a[mi][2],
                                     a[mi][3], bb[ni][0], bb[ni][1]);
                }
            }
        }

        #pragma unroll
        for (int wv = 0; wv < 2; wv++)
            #pragma unroll
            for (int mi = 0; mi < 2; mi++) {
                const int r0 = mtile * 64 + wm * 32 + mi * 16;
                #pragma unroll
                for (int ni = 0; ni < 2; ni++) {
                    const int o0 = otile * 32 + wn * 16 + ni * 8 + tg * 2;
                    float2 v0 = { acc[wv][mi][ni][0], acc[wv][mi][ni][1] };
                    float2 v1 = { acc[wv][mi][ni][2], acc[wv][mi][ni][3] };
                    *(float2*)&g_uv_p[seg][wv][l][r0 + g][o0]     = v0;
                    *(float2*)&g_uv_p[seg][wv][l][r0 + g + 8][o0] = v1;
                }
            }
    }
}

// ---------------------------------------------------------------------------
// h_new = sigmoid(alpha)*tanh(phi) + sigmoid(beta)*h  -> d_out[0:H_SIZE]
// Sums the two gate split-K partials and adds biases.  float4 vectorized.
// ---------------------------------------------------------------------------
__global__ __launch_bounds__(256)
void hnew_kernel(const float* __restrict__ h,
                 const float* __restrict__ phi_b, const float* __restrict__ alpha_b,
                 const float* __restrict__ beta_b,
                 float* __restrict__ out)
{
    const int idx = blockIdx.x * blockDim.x + threadIdx.x;   // float4 index
    if (idx >= H_SIZE4) return;
    const float4* g0 = (const float4*)&g_gate_p[0][0][0][0][0];
    const float4* g1 = (const float4*)&g_gate_p[1][0][0][0][0];

    const int base = idx * 4;
    const int l = base >> 16;          // BAT*STW = 65536
    const int o = base & (STW - 1);
    const float4 pb = *(const float4*)(phi_b   + l * STW + o);
    const float4 ab = *(const float4*)(alpha_b + l * STW + o);
    const float4 bbv = *(const float4*)(beta_b + l * STW + o);

    float4 p0 = g0[idx],               p1 = g1[idx];
    float4 a0 = g0[H_SIZE4 + idx],     a1 = g1[H_SIZE4 + idx];
    float4 b0 = g0[2 * H_SIZE4 + idx], b1 = g1[2 * H_SIZE4 + idx];
    float4 hv = ((const float4*)h)[idx];

    float4 o4;
    o4.x = sigmoidf_(a0.x + a1.x + ab.x) * tanhf(p0.x + p1.x + pb.x) + sigmoidf_(b0.x + b1.x + bbv.x) * hv.x;
    o4.y = sigmoidf_(a0.y + a1.y + ab.y) * tanhf(p0.y + p1.y + pb.y) + sigmoidf_(b0.y + b1.y + bbv.y) * hv.y;
    o4.z = sigmoidf_(a0.z + a1.z + ab.z) * tanhf(p0.z + p1.z + pb.z) + sigmoidf_(b0.z + b1.z + bbv.z) * hv.z;
    o4.w = sigmoidf_(a0.w + a1.w + ab.w) * tanhf(p0.w + p1.w + pb.w) + sigmoidf_(b0.w + b1.w + bbv.w) * hv.w;
    ((float4*)out)[idx] = o4;
}

// ---------------------------------------------------------------------------
// uv_h GEMM: the h_new-dependent third of u/v (K in [0,512) of wv).
// u+v fused (share A tile).  grid: (otile=8, mtile=2, l=4) = 64 blocks.
// Writes segment slot 2 of g_uv_p.
// ---------------------------------------------------------------------------
__global__ __launch_bounds__(128)
void uv_h_gemm(const float* __restrict__ hn,
               const float* __restrict__ u_w, const float* __restrict__ v_w)
{
    extern __shared__ float smem_dyn[];
    float (*As)[64][36]    = (float(*)[64][36])smem_dyn;
    float (*Bs)[2][32][36] = (float(*)[2][32][36])(smem_dyn + 3 * 64 * 36);

    const int l     = blockIdx.z;
    const int mtile = blockIdx.y;
    const int otile = blockIdx.x;

    const int t = threadIdx.x;
    const int w = t >> 5, lane = t & 31;
    const int wm = w >> 1, wn = w & 1;
    const int g = lane >> 2, tg = lane & 3;

    const float* Wuv[2] = { u_w + (size_t)l * RW * DW,
                            v_w + (size_t)l * RW * DW };

    float acc[2][2][2][4];
    #pragma unroll
    for (int wv = 0; wv < 2; wv++)
        #pragma unroll
        for (int mi = 0; mi < 2; mi++)
            #pragma unroll
            for (int ni = 0; ni < 2; ni++)
                #pragma unroll
                for (int r = 0; r < 4; r++) acc[wv][mi][ni][r] = 0.0f;

    auto load_chunk = [&](int kt, int s) {
        #pragma unroll
        for (int i = 0; i < 4; i++) {
            const int idx = i * 128 + t;
            const int row = idx >> 3, ch = idx & 7;
            cp16(&As[s][row][ch * 4],
                 hn + ((size_t)l * BAT + mtile * 64 + row) * STW + kt + ch * 4);
        }
        #pragma unroll
        for (int i = 0; i < 4; i++) {
            const int idx = i * 128 + t;
            const int wv  = idx >> 8;
            const int rem = idx & 255;
            const int row = rem >> 3, ch = rem & 7;
            cp16(&Bs[s][wv][row][ch * 4],
                 Wuv[wv] + (size_t)(otile * 32 + row) * DW + kt + ch * 4);
        }
        cp_commit();
    };

    load_chunk(0, 0);
    load_chunk(KC, 1);
    for (int it = 0; it < NCH_UV; ++it) {
        const int s = it % 3;
        if (it + 1 < NCH_UV) cp_wait<1>(); else cp_wait<0>();
        __syncthreads();
        if (it + 2 < NCH_UV) load_chunk((it + 2) * KC, (it + 2) % 3);

        #pragma unroll
        for (int ks = 0; ks < 4; ks++) {
            const int k0 = ks * 8;
            unsigned a[2][4];
            #pragma unroll
            for (int mi = 0; mi < 2; mi++) {
                const int r0 = wm * 32 + mi * 16;
                a[mi][0] = __float_as_uint(As[s][r0 + g][k0 + tg]);
                a[mi][1] = __float_as_uint(As[s][r0 + g + 8][k0 + tg]);
                a[mi][2] = __float_as_uint(As[s][r0 + g][k0 + tg + 4]);
                a[mi][3] = __float_as_uint(As[s][r0 + g + 8][k0 + tg + 4]);
            }
            #pragma unroll
            for (int wv = 0; wv < 2; wv++) {
                unsigned bb[2][2];
                #pragma unroll
                for (int ni = 0; ni < 2; ni++) {
                    const int n0 = wn * 16 + ni * 8 + g;
                    bb[ni][0] = __float_as_uint(Bs[s][wv][n0][k0 + tg]);
                    bb[ni][1] = __float_as_uint(Bs[s][wv][n0][k0 + tg + 4]);
                }
                #pragma unroll
                for (int mi = 0; mi < 2; mi++)
                    #pragma unroll
                    for (int ni = 0; ni < 2; ni++)
                        mma_tf32(acc[wv][mi][ni], a[mi][0], a[mi][1], a[mi][2],
                                 a[mi][3], bb[ni][0], bb[ni][1]);
            }
        }
    }

    #pragma unroll
    for (int wv = 0; wv < 2; wv++)
        #pragma unroll
        for (int mi = 0; mi < 2; mi++) {
            const int r0 = mtile * 64 + wm * 32 + mi * 16;
            #pragma unroll
            for (int ni = 0; ni < 2; ni++) {
                const int o0 = otile * 32 + wn * 16 + ni * 8 + tg * 2;
                float2 v0 = { acc[wv][mi][ni][0], acc[wv][mi][ni][1] };
                float2 v1 = { acc[wv][mi][ni][2], acc[wv][mi][ni][3] };
                *(float2*)&g_uv_p[2][wv][l][r0 + g][o0]     = v0;
                *(float2*)&g_uv_p[2][wv][l][r0 + g + 8][o0] = v1;
            }
        }
}

// ---------------------------------------------------------------------------
// M update, fused across all 4 levels (each M element read exactly once).
// Sums the THREE u/v segment partials + biases at staging.  Touch-once
// traffic -> evict-first streaming (__ldcs/__stcs).  R9-proven shape
// (simplest of the 5 equal-speed variants tried): grid (8,128), 256 thr.
// ---------------------------------------------------------------------------
__global__ __launch_bounds__(256)
void m_update(const float* __restrict__ M,
              const float* __restrict__ gamma_logits,
              const float* __restrict__ eta_logits,
              const float* __restrict__ u_b, const float* __restrict__ v_b,
              float* __restrict__ out)
{
    __shared__ float sv[4][256];
    __shared__ float su[4][32];
    __shared__ float sg[4], se[4];

    const int b  = blockIdx.y;
    const int ic = blockIdx.x;     // 0..7: 32-row chunk of i
    const int t  = threadIdx.x;

    for (int e = t; e < 1024; e += 256) {
        int l = e >> 8, j = e & 255;
        sv[l][j] = g_uv_p[0][1][l][b][j] + g_uv_p[1][1][l][b][j]
                 + g_uv_p[2][1][l][b][j] + v_b[l * RW + j];
    }
    if (t < 128) {
        int l = t >> 5, i = t & 31;
        int r = ic * 32 + i;
        su[l][i] = g_uv_p[0][0][l][b][r] + g_uv_p[1][0][l][b][r]
                 + g_uv_p[2][0][l][b][r] + u_b[l * RW + r];
    }
    if (t < 4) { sg[t] = sigmoidf_(gamma_logits[t]); se[t] = sigmoidf_(eta_logits[t]); }
    __syncthreads();

    float* mout = out + H_SIZE;

    #pragma unroll 1
    for (int it = 0; it < 8; it++) {
        const int p  = it * 256 + t;
        const int i  = p >> 6;              // 0..31
        const int j4 = (p & 63) << 2;       // 0..252
        const size_t base = ((size_t)b * RW + ic * 32 + i) * CW + j4;

        float4 m[4];
        #pragma unroll
        for (int l = 0; l < 4; l++)
            m[l] = __ldcs((const float4*)(M + (size_t)l * M_LVL_STRIDE + base));

        #pragma unroll
        for (int l = 0; l < 4; l++) {
            const int lu = (l == 0) ? 0 : l - 1;
            const int ld = (l == 3) ? 3 : l + 1;
            const float gg = sg[l];
            const float ue = se[l] * su[l][i];
            const float4 v = *(const float4*)&sv[l][j4];
            float4 o;
            o.x = (1.0f - gg) * m[l].x + 0.5f * gg * (m[lu].x + m[ld].x) + ue * v.x;
            o.y = (1.0f - gg) * m[l].y + 0.5f * gg * (m[lu].y + m[ld].y) + ue * v.y;
            o.z = (1.0f - gg) * m[l].z + 0.5f * gg * (m[lu].z + m[ld].z) + ue * v.z;
            o.w = (1.0f - gg) * m[l].w + 0.5f * gg * (m[lu].w + m[ld].w) + ue * v.w;
            __stcs((float4*)(mout + (size_t)l * M_LVL_STRIDE + base), o);
        }
    }
}

// ---------------------------------------------------------------------------
extern "C" void kernel_launch(void* const* d_in, const int* in_sizes, int n_in,
                              void* d_out, int out_size)
{
    const float* x       = (const float*)d_in[0];
    const float* c       = (const float*)d_in[1];
    const float* h       = (const float*)d_in[2];
    const float* M       = (const float*)d_in[3];
    const float* phi_w   = (const float*)d_in[4];
    const float* phi_b   = (const float*)d_in[5];
    const float* alpha_w = (const float*)d_in[6];
    const float* alpha_b = (const float*)d_in[7];
    const float* beta_w  = (const float*)d_in[8];
    const float* beta_b  = (const float*)d_in[9];
    const float* u_w     = (const float*)d_in[10];
    const float* u_b     = (const float*)d_in[11];
    const float* v_w     = (const float*)d_in[12];
    const float* v_b     = (const float*)d_in[13];
    const float* gamma_l = (const float*)d_in[14];
    const float* eta_l   = (const float*)d_in[15];

    float* out = (float*)d_out;

    // idempotent; first calls happen on the uncaptured correctness run
    cudaFuncSetAttribute(gate_uvxc_gemm, cudaFuncAttributeMaxDynamicSharedMemorySize,
                         GATE_SMEM_BYTES);
    cudaFuncSetAttribute(uv_h_gemm, cudaFuncAttributeMaxDynamicSharedMemorySize,
                         UV_SMEM_BYTES);

    // 1. COMBINED: gate GEMMs (split-K x2) + uv_xc GEMMs (h-independent 2/3
    //    of u/v K-range) in one 384-block launch -> g_gate_p, g_uv_p[0..1]
    gate_uvxc_gemm<<<dim3(24, 4, 4), 128, GATE_SMEM_BYTES>>>(
        x, c, h, phi_w, alpha_w, beta_w, u_w, v_w);
    // 2. h_new (sums gate partials + biases) -> out[0:H_SIZE]
    hnew_kernel<<<H_SIZE4 / 256, 256>>>(h, phi_b, alpha_b, beta_b, out);
    // 3. uv_h: h_new-dependent third of u/v -> g_uv_p[2]
    uv_h_gemm<<<dim3(8, 2, 4), 128, UV_SMEM_BYTES>>>(out, u_w, v_w);
    // 4. fused 4-level M update (sums 3 u/v partials + biases) -> out[H_SIZE:]
    m_update<<<dim3(8, 128), 256>>>(M, gamma_l, eta_l, u_b, v_b, out);
}

// round 16
// speedup vs baseline: 1.0879x; 1.0879x over previous
#include <cuda_runtime.h>
#include <math.h>

#define LVL 4
#define BAT 128
#define INW 512
#define CTXW 512
#define STW 512
#define RW 256
#define CW 256
#define DW 1536
#define KC 32
#define KHALF 768                     /* K per gate split-K block */
#define NCH_GATE (KHALF/KC)           /* 24 chunks */
#define NCH_UV 16                     /* 512 K per uv segment */
#define H_SIZE (LVL*BAT*STW)          /* 262144 */
#define H_SIZE4 (H_SIZE/4)            /* 65536 */
#define M_LVL_STRIDE (BAT*RW*CW)      /* 8388608 */

#define GATE_SMEM_BYTES  (3 * (64 * 36 + 3 * 32 * 36) * 4)   /* 69120 */
#define UV_SMEM_BYTES    (3 * (64 * 36 + 2 * 32 * 36) * 4)   /* 55296 */

// scratch (allocation-free rule: __device__ globals)
__device__ __align__(16) float g_gate_p[2][3][LVL][BAT][STW];  // gate split-K partials (6 MB)
__device__ __align__(16) float g_uv_p[3][2][LVL][BAT][RW];     // u/v 3-segment partials (3 MB)

__device__ __forceinline__ float sigmoidf_(float x) { return 1.0f / (1.0f + __expf(-x)); }

// PDL primitives (sm_90+)
__device__ __forceinline__ void pdl_trigger() {
    asm volatile("griddepcontrol.launch_dependents;");
}
__device__ __forceinline__ void pdl_wait() {
    asm volatile("griddepcontrol.wait;" ::: "memory");
}

__device__ __forceinline__ void mma_tf32(float* d, unsigned a0, unsigned a1,
                                         unsigned a2, unsigned a3,
                                         unsigned b0, unsigned b1)
{
    asm volatile(
        "mma.sync.aligned.m16n8k8.row.col.f32.tf32.tf32.f32 "
        "{%0,%1,%2,%3}, {%4,%5,%6,%7}, {%8,%9}, {%0,%1,%2,%3};\n"
        : "+f"(d[0]), "+f"(d[1]), "+f"(d[2]), "+f"(d[3])
        : "r"(a0), "r"(a1), "r"(a2), "r"(a3), "r"(b0), "r"(b1));
}

__device__ __forceinline__ void cp16(void* dst, const void* src) {
    unsigned ds = (unsigned)__cvta_generic_to_shared(dst);
    asm volatile("cp.async.ca.shared.global [%0], [%1], 16;" :: "r"(ds), "l"(src));
}
__device__ __forceinline__ void cp16cg(void* dst, const void* src) {
    unsigned ds = (unsigned)__cvta_generic_to_shared(dst);
    asm volatile("cp.async.cg.shared.global [%0], [%1], 16;" :: "r"(ds), "l"(src));
}
__device__ __forceinline__ void cp_commit() { asm volatile("cp.async.commit_group;"); }
template<int N> __device__ __forceinline__ void cp_wait() {
    asm volatile("cp.async.wait_group %0;" :: "n"(N));
}

// ---------------------------------------------------------------------------
// FUSED gate GEMM (R13/R14-proven), split-K x2.  Triggers PDL at TOP so
// uv_xc blocks become launch-eligible and fill SM space as gate blocks
// retire (the 1-vs-2-blocks/SM imbalance tail).
// grid: (otile=16, y=mtile*2+kh=4, z=l=4) = 256 blocks, 128 thr, 69KB dyn.
// ---------------------------------------------------------------------------
__global__ __launch_bounds__(128)
void gate_gemm(const float* __restrict__ x, const float* __restrict__ c,
               const float* __restrict__ h,
               const float* __restrict__ phi_w, const float* __restrict__ alpha_w,
               const float* __restrict__ beta_w)
{
    pdl_trigger();   // uv_xc is h/gate-independent; let it launch as space frees

    extern __shared__ float smem_dyn[];
    float (*As)[64][36]    = (float(*)[64][36])smem_dyn;
    float (*Bs)[3][32][36] = (float(*)[3][32][36])(smem_dyn + 3 * 64 * 36);

    const int l     = blockIdx.z;
    const int mtile = blockIdx.y >> 1;
    const int kh    = blockIdx.y & 1;
    const int otile = blockIdx.x;
    const int kbase = kh * KHALF;

    const int t = threadIdx.x;
    const int w = t >> 5, lane = t & 31;
    const int wm = w >> 1, wn = w & 1;
    const int g = lane >> 2, tg = lane & 3;

    const float* Wg[3] = { phi_w   + (size_t)l * STW * DW,
                           alpha_w + (size_t)l * STW * DW,
                           beta_w  + (size_t)l * STW * DW };

    float acc[3][2][2][4];
    #pragma unroll
    for (int ga = 0; ga < 3; ga++)
        #pragma unroll
        for (int mi = 0; mi < 2; mi++)
            #pragma unroll
            for (int ni = 0; ni < 2; ni++)
                #pragma unroll
                for (int r = 0; r < 4; r++) acc[ga][mi][ni][r] = 0.0f;

    auto load_chunk = [&](int kt, int s) {
        #pragma unroll
        for (int i = 0; i < 4; i++) {
            const int idx = i * 128 + t;
            const int row = idx >> 3, ch = idx & 7;
            const int k = kt + ch * 4;
            const int b = mtile * 64 + row;
            const float* src;
            if (k < INW)              src = x + (size_t)b * INW + k;
            else if (k < INW + CTXW)  src = c + (size_t)b * CTXW + (k - INW);
            else                      src = h + ((size_t)l * BAT + b) * STW + (k - INW - CTXW);
            cp16(&As[s][row][ch * 4], src);
        }
        #pragma unroll
        for (int i = 0; i < 6; i++) {
            const int idx = i * 128 + t;
            const int ga  = idx >> 8;
            const int rem = idx & 255;
            const int row = rem >> 3, ch = rem & 7;
            cp16(&Bs[s][ga][row][ch * 4],
                 Wg[ga] + (size_t)(otile * 32 + row) * DW + kt + ch * 4);
        }
        cp_commit();
    };

    // 3-stage pipeline (wait<1> with 1 pending group would not wait — the
    // R6-class bug — hence wait<0> on the last iteration).
    load_chunk(kbase, 0);
    load_chunk(kbase + KC, 1);
    for (int it = 0; it < NCH_GATE; ++it) {
        const int s = it % 3;
        if (it + 1 < NCH_GATE) cp_wait<1>(); else cp_wait<0>();
        __syncthreads();
        if (it + 2 < NCH_GATE) load_chunk(kbase + (it + 2) * KC, (it + 2) % 3);

        #pragma unroll
        for (int ks = 0; ks < 4; ks++) {
            const int k0 = ks * 8;
            unsigned a[2][4];
            #pragma unroll
            for (int mi = 0; mi < 2; mi++) {
                const int r0 = wm * 32 + mi * 16;
                a[mi][0] = __float_as_uint(As[s][r0 + g][k0 + tg]);
                a[mi][1] = __float_as_uint(As[s][r0 + g + 8][k0 + tg]);
                a[mi][2] = __float_as_uint(As[s][r0 + g][k0 + tg + 4]);
                a[mi][3] = __float_as_uint(As[s][r0 + g + 8][k0 + tg + 4]);
            }
            #pragma unroll
            for (int ga = 0; ga < 3; ga++) {
                unsigned bb[2][2];
                #pragma unroll
                for (int ni = 0; ni < 2; ni++) {
                    const int n0 = wn * 16 + ni * 8 + g;
                    bb[ni][0] = __float_as_uint(Bs[s][ga][n0][k0 + tg]);
                    bb[ni][1] = __float_as_uint(Bs[s][ga][n0][k0 + tg + 4]);
                }
                #pragma unroll
                for (int mi = 0; mi < 2; mi++)
                    #pragma unroll
                    for (int ni = 0; ni < 2; ni++)
                        mma_tf32(acc[ga][mi][ni], a[mi][0], a[mi][1], a[mi][2],
                                 a[mi][3], bb[ni][0], bb[ni][1]);
            }
        }
    }

    #pragma unroll
    for (int ga = 0; ga < 3; ga++)
        #pragma unroll
        for (int mi = 0; mi < 2; mi++) {
            const int r0 = mtile * 64 + wm * 32 + mi * 16;
            #pragma unroll
            for (int ni = 0; ni < 2; ni++) {
                const int o0 = otile * 32 + wn * 16 + ni * 8 + tg * 2;
                float2 v0 = { acc[ga][mi][ni][0], acc[ga][mi][ni][1] };
                float2 v1 = { acc[ga][mi][ni][2], acc[ga][mi][ni][3] };
                *(float2*)&g_gate_p[kh][ga][l][r0 + g][o0]     = v0;
                *(float2*)&g_gate_p[kh][ga][l][r0 + g + 8][o0] = v1;
            }
        }
}

// ---------------------------------------------------------------------------
// uv_xc GEMM: h-independent 2/3 of u/v (K in [512,1536) of wv = x|c).
// NO top wait (reads nothing from gate).  End-of-kernel pdl_wait() makes
// "uv_xc complete" imply "gate complete" — prevents the PDL chain from
// telescoping past an unfinished gate.  u+v share the A tile.
// grid: (otile=8, y=mtile*2+seg=4, z=l=4) = 128 blocks, 55KB dyn.
// seg=0 -> K[512,1024) (x), seg=1 -> K[1024,1536) (c).  Writes g_uv_p[seg].
// ---------------------------------------------------------------------------
__global__ __launch_bounds__(128)
void uvxc_gemm(const float* __restrict__ x, const float* __restrict__ c,
               const float* __restrict__ u_w, const float* __restrict__ v_w)
{
    extern __shared__ float smem_dyn[];
    float (*As)[64][36]    = (float(*)[64][36])smem_dyn;
    float (*Bs)[2][32][36] = (float(*)[2][32][36])(smem_dyn + 3 * 64 * 36);

    const int l     = blockIdx.z;
    const int mtile = blockIdx.y >> 1;
    const int seg   = blockIdx.y & 1;
    const int otile = blockIdx.x;
    const int kbase = STW + seg * 512;

    const int t = threadIdx.x;
    const int w = t >> 5, lane = t & 31;
    const int wm = w >> 1, wn = w & 1;
    const int g = lane >> 2, tg = lane & 3;

    const float* Wuv[2] = { u_w + (size_t)l * RW * DW,
                            v_w + (size_t)l * RW * DW };

    float acc[2][2][2][4];
    #pragma unroll
    for (int wv = 0; wv < 2; wv++)
        #pragma unroll
        for (int mi = 0; mi < 2; mi++)
            #pragma unroll
            for (int ni = 0; ni < 2; ni++)
                #pragma unroll
                for (int r = 0; r < 4; r++) acc[wv][mi][ni][r] = 0.0f;

    auto load_chunk = [&](int kt, int s) {
        #pragma unroll
        for (int i = 0; i < 4; i++) {
            const int idx = i * 128 + t;
            const int row = idx >> 3, ch = idx & 7;
            const int k = kt + ch * 4;          // in [512,1536)
            const int b = mtile * 64 + row;
            const float* src = (k < STW + INW)
                ? x + (size_t)b * INW + (k - STW)
                : c + (size_t)b * CTXW + (k - STW - INW);
            cp16(&As[s][row][ch * 4], src);
        }
        #pragma unroll
        for (int i = 0; i < 4; i++) {
            const int idx = i * 128 + t;
            const int wv  = idx >> 8;
            const int rem = idx & 255;
            const int row = rem >> 3, ch = rem & 7;
            cp16(&Bs[s][wv][row][ch * 4],
                 Wuv[wv] + (size_t)(otile * 32 + row) * DW + kt + ch * 4);
        }
        cp_commit();
    };

    load_chunk(kbase, 0);
    load_chunk(kbase + KC, 1);
    for (int it = 0; it < NCH_UV; ++it) {
        const int s = it % 3;
        if (it + 1 < NCH_UV) cp_wait<1>(); else cp_wait<0>();
        __syncthreads();
        if (it + 2 < NCH_UV) load_chunk(kbase + (it + 2) * KC, (it + 2) % 3);

        #pragma unroll
        for (int ks = 0; ks < 4; ks++) {
            const int k0 = ks * 8;
            unsigned a[2][4];
            #pragma unroll
            for (int mi = 0; mi < 2; mi++) {
                const int r0 = wm * 32 + mi * 16;
                a[mi][0] = __float_as_uint(As[s][r0 + g][k0 + tg]);
                a[mi][1] = __float_as_uint(As[s][r0 + g + 8][k0 + tg]);
                a[mi][2] = __float_as_uint(As[s][r0 + g][k0 + tg + 4]);
                a[mi][3] = __float_as_uint(As[s][r0 + g + 8][k0 + tg + 4]);
            }
            #pragma unroll
            for (int wv = 0; wv < 2; wv++) {
                unsigned bb[2][2];
                #pragma unroll
                for (int ni = 0; ni < 2; ni++) {
                    const int n0 = wn * 16 + ni * 8 + g;
                    bb[ni][0] = __float_as_uint(Bs[s][wv][n0][k0 + tg]);
                    bb[ni][1] = __float_as_uint(Bs[s][wv][n0][k0 + tg + 4]);
                }
                #pragma unroll
                for (int mi = 0; mi < 2; mi++)
                    #pragma unroll
                    for (int ni = 0; ni < 2; ni++)
                        mma_tf32(acc[wv][mi][ni], a[mi][0], a[mi][1], a[mi][2],
                                 a[mi][3], bb[ni][0], bb[ni][1]);
            }
        }
    }

    pdl_wait();      // ensure gate is complete before this grid can complete
    pdl_trigger();   // allow hnew to launch

    #pragma unroll
    for (int wv = 0; wv < 2; wv++)
        #pragma unroll
        for (int mi = 0; mi < 2; mi++) {
            const int r0 = mtile * 64 + wm * 32 + mi * 16;
            #pragma unroll
            for (int ni = 0; ni < 2; ni++) {
                const int o0 = otile * 32 + wn * 16 + ni * 8 + tg * 2;
                float2 v0 = { acc[wv][mi][ni][0], acc[wv][mi][ni][1] };
                float2 v1 = { acc[wv][mi][ni][2], acc[wv][mi][ni][3] };
                *(float2*)&g_uv_p[seg][wv][l][r0 + g][o0]     = v0;
                *(float2*)&g_uv_p[seg][wv][l][r0 + g + 8][o0] = v1;
            }
        }
}

// ---------------------------------------------------------------------------
// h_new = sigmoid(alpha)*tanh(phi) + sigmoid(beta)*h  -> d_out[0:H_SIZE]
// pdl_wait: uv_xc complete (which implies gate complete).
// ---------------------------------------------------------------------------
__global__ __launch_bounds__(256)
void hnew_kernel(const float* __restrict__ h,
                 const float* __restrict__ phi_b, const float* __restrict__ alpha_b,
                 const float* __restrict__ beta_b,
                 float* __restrict__ out)
{
    pdl_wait();
    pdl_trigger();

    const int idx = blockIdx.x * blockDim.x + threadIdx.x;   // float4 index
    if (idx >= H_SIZE4) return;
    const float4* g0 = (const float4*)&g_gate_p[0][0][0][0][0];
    const float4* g1 = (const float4*)&g_gate_p[1][0][0][0][0];

    const int base = idx * 4;
    const int l = base >> 16;          // BAT*STW = 65536
    const int o = base & (STW - 1);
    const float4 pb = *(const float4*)(phi_b   + l * STW + o);
    const float4 ab = *(const float4*)(alpha_b + l * STW + o);
    const float4 bbv = *(const float4*)(beta_b + l * STW + o);

    float4 p0 = g0[idx],               p1 = g1[idx];
    float4 a0 = g0[H_SIZE4 + idx],     a1 = g1[H_SIZE4 + idx];
    float4 b0 = g0[2 * H_SIZE4 + idx], b1 = g1[2 * H_SIZE4 + idx];
    float4 hv = ((const float4*)h)[idx];

    float4 o4;
    o4.x = sigmoidf_(a0.x + a1.x + ab.x) * tanhf(p0.x + p1.x + pb.x) + sigmoidf_(b0.x + b1.x + bbv.x) * hv.x;
    o4.y = sigmoidf_(a0.y + a1.y + ab.y) * tanhf(p0.y + p1.y + pb.y) + sigmoidf_(b0.y + b1.y + bbv.y) * hv.y;
    o4.z = sigmoidf_(a0.z + a1.z + ab.z) * tanhf(p0.z + p1.z + pb.z) + sigmoidf_(b0.z + b1.z + bbv.z) * hv.z;
    o4.w = sigmoidf_(a0.w + a1.w + ab.w) * tanhf(p0.w + p1.w + pb.w) + sigmoidf_(b0.w + b1.w + bbv.w) * hv.w;
    ((float4*)out)[idx] = o4;
}

// ---------------------------------------------------------------------------
// uv_h GEMM: h_new-dependent third of u/v (K in [0,512)).  u+v share A.
// pdl_wait at top (needs h_new).  grid: (8, 2, 4) = 64 blocks, 55KB dyn.
// Writes g_uv_p[2].
// ---------------------------------------------------------------------------
__global__ __launch_bounds__(128)
void uvh_gemm(const float* __restrict__ hn,
              const float* __restrict__ u_w, const float* __restrict__ v_w)
{
    pdl_wait();

    extern __shared__ float smem_dyn[];
    float (*As)[64][36]    = (float(*)[64][36])smem_dyn;
    float (*Bs)[2][32][36] = (float(*)[2][32][36])(smem_dyn + 3 * 64 * 36);

    const int l     = blockIdx.z;
    const int mtile = blockIdx.y;
    const int otile = blockIdx.x;

    const int t = threadIdx.x;
    const int w = t >> 5, lane = t & 31;
    const int wm = w >> 1, wn = w & 1;
    const int g = lane >> 2, tg = lane & 3;

    const float* Wuv[2] = { u_w + (size_t)l * RW * DW,
                            v_w + (size_t)l * RW * DW };

    float acc[2][2][2][4];
    #pragma unroll
    for (int wv = 0; wv < 2; wv++)
        #pragma unroll
        for (int mi = 0; mi < 2; mi++)
            #pragma unroll
            for (int ni = 0; ni < 2; ni++)
                #pragma unroll
                for (int r = 0; r < 4; r++) acc[wv][mi][ni][r] = 0.0f;

    auto load_chunk = [&](int kt, int s) {
        #pragma unroll
        for (int i = 0; i < 4; i++) {
            const int idx = i * 128 + t;
            const int row = idx >> 3, ch = idx & 7;
            cp16(&As[s][row][ch * 4],
                 hn + ((size_t)l * BAT + mtile * 64 + row) * STW + kt + ch * 4);
        }
        #pragma unroll
        for (int i = 0; i < 4; i++) {
            const int idx = i * 128 + t;
            const int wv  = idx >> 8;
            const int rem = idx & 255;
            const int row = rem >> 3, ch = rem & 7;
            cp16(&Bs[s][wv][row][ch * 4],
                 Wuv[wv] + (size_t)(otile * 32 + row) * DW + kt + ch * 4);
        }
        cp_commit();
    };

    load_chunk(0, 0);
    load_chunk(KC, 1);
    for (int it = 0; it < NCH_UV; ++it) {
        const int s = it % 3;
        if (it + 1 < NCH_UV) cp_wait<1>(); else cp_wait<0>();
        __syncthreads();
        if (it + 2 < NCH_UV) load_chunk((it + 2) * KC, (it + 2) % 3);

        #pragma unroll
        for (int ks = 0; ks < 4; ks++) {
            const int k0 = ks * 8;
            unsigned a[2][4];
            #pragma unroll
            for (int mi = 0; mi < 2; mi++) {
                const int r0 = wm * 32 + mi * 16;
                a[mi][0] = __float_as_uint(As[s][r0 + g][k0 + tg]);
                a[mi][1] = __float_as_uint(As[s][r0 + g + 8][k0 + tg]);
                a[mi][2] = __float_as_uint(As[s][r0 + g][k0 + tg + 4]);
                a[mi][3] = __float_as_uint(As[s][r0 + g + 8][k0 + tg + 4]);
            }
            #pragma unroll
            for (int wv = 0; wv < 2; wv++) {
                unsigned bb[2][2];
                #pragma unroll
                for (int ni = 0; ni < 2; ni++) {
                    const int n0 = wn * 16 + ni * 8 + g;
                    bb[ni][0] = __float_as_uint(Bs[s][wv][n0][k0 + tg]);
                    bb[ni][1] = __float_as_uint(Bs[s][wv][n0][k0 + tg + 4]);
                }
                #pragma unroll
                for (int mi = 0; mi < 2; mi++)
                    #pragma unroll
                    for (int ni = 0; ni < 2; ni++)
                        mma_tf32(acc[wv][mi][ni], a[mi][0], a[mi][1], a[mi][2],
                                 a[mi][3], bb[ni][0], bb[ni][1]);
            }
        }
    }

    pdl_trigger();   // allow m_update to launch during our epilogue

    #pragma unroll
    for (int wv = 0; wv < 2; wv++)
        #pragma unroll
        for (int mi = 0; mi < 2; mi++) {
            const int r0 = mtile * 64 + wm * 32 + mi * 16;
            #pragma unroll
            for (int ni = 0; ni < 2; ni++) {
                const int o0 = otile * 32 + wn * 16 + ni * 8 + tg * 2;
                float2 v0 = { acc[wv][mi][ni][0], acc[wv][mi][ni][1] };
                float2 v1 = { acc[wv][mi][ni][2], acc[wv][mi][ni][3] };
                *(float2*)&g_uv_p[2][wv][l][r0 + g][o0]     = v0;
                *(float2*)&g_uv_p[2][wv][l][r0 + g + 8][o0] = v1;
            }
        }
}

// ---------------------------------------------------------------------------
// M update, fused across all 4 levels (each M element read exactly once).
// PDL: prefetch the first M stage (independent of u/v) via cp.async BEFORE
// pdl_wait, overlapping the DRAM ramp with uv_h's tail.  Then sums the three
// u/v segment partials + biases, and streams with __ldcs/__stcs (R9 shape).
// grid: (ichunk=8, b=128), 256 threads.
// ---------------------------------------------------------------------------
__global__ __launch_bounds__(256)
void m_update(const float* __restrict__ M,
              const float* __restrict__ gamma_logits,
              const float* __restrict__ eta_logits,
              const float* __restrict__ u_b, const float* __restrict__ v_b,
              float* __restrict__ out)
{
    __shared__ float4 mpre[4][256];     // prefetched it=0 M tiles (16 KB)
    __shared__ float sv[4][256];
    __shared__ float su[4][32];
    __shared__ float sg[4], se[4];

    const int b  = blockIdx.y;
    const int ic = blockIdx.x;     // 0..7: 32-row chunk of i
    const int t  = threadIdx.x;

    // prefetch it=0 M (independent of predecessors) BEFORE the PDL wait
    {
        const int i  = t >> 6;
        const int j4 = (t & 63) << 2;
        const size_t base = ((size_t)b * RW + ic * 32 + i) * CW + j4;
        #pragma unroll
        for (int l = 0; l < 4; l++)
            cp16cg(&mpre[l][t], M + (size_t)l * M_LVL_STRIDE + base);
        cp_commit();
    }

    pdl_wait();   // u/v partials now complete and visible

    for (int e = t; e < 1024; e += 256) {
        int l = e >> 8, j = e & 255;
        sv[l][j] = g_uv_p[0][1][l][b][j] + g_uv_p[1][1][l][b][j]
                 + g_uv_p[2][1][l][b][j] + v_b[l * RW + j];
    }
    if (t < 128) {
        int l = t >> 5, i = t & 31;
        int r = ic * 32 + i;
        su[l][i] = g_uv_p[0][0][l][b][r] + g_uv_p[1][0][l][b][r]
                 + g_uv_p[2][0][l][b][r] + u_b[l * RW + r];
    }
    if (t < 4) { sg[t] = sigmoidf_(gamma_logits[t]); se[t] = sigmoidf_(eta_logits[t]); }
    __syncthreads();
    cp_wait<0>();   // own prefetch complete (per-thread; reads own words only)

    float* mout = out + H_SIZE;

    // peeled it = 0 (from prefetch buffer)
    {
        const int i  = t >> 6;
        const int j4 = (t & 63) << 2;
        const size_t base = ((size_t)b * RW + ic * 32 + i) * CW + j4;
        float4 m[4];
        #pragma unroll
        for (int l = 0; l < 4; l++) m[l] = mpre[l][t];
        #pragma unroll
        for (int l = 0; l < 4; l++) {
            const int lu = (l == 0) ? 0 : l - 1;
            const int ld = (l == 3) ? 3 : l + 1;
            const float gg = sg[l];
            const float ue = se[l] * su[l][i];
            const float4 v = *(const float4*)&sv[l][j4];
            float4 o;
            o.x = (1.0f - gg) * m[l].x + 0.5f * gg * (m[lu].x + m[ld].x) + ue * v.x;
            o.y = (1.0f - gg) * m[l].y + 0.5f * gg * (m[lu].y + m[ld].y) + ue * v.y;
            o.z = (1.0f - gg) * m[l].z + 0.5f * gg * (m[lu].z + m[ld].z) + ue * v.z;
            o.w = (1.0f - gg) * m[l].w + 0.5f * gg * (m[lu].w + m[ld].w) + ue * v.w;
            __stcs((float4*)(mout + (size_t)l * M_LVL_STRIDE + base), o);
        }
    }

    #pragma unroll 1
    for (int it = 1; it < 8; it++) {
        const int p  = it * 256 + t;
        const int i  = p >> 6;
        const int j4 = (p & 63) << 2;
        const size_t base = ((size_t)b * RW + ic * 32 + i) * CW + j4;

        float4 m[4];
        #pragma unroll
        for (int l = 0; l < 4; l++)
            m[l] = __ldcs((const float4*)(M + (size_t)l * M_LVL_STRIDE + base));

        #pragma unroll
        for (int l = 0; l < 4; l++) {
            const int lu = (l == 0) ? 0 : l - 1;
            const int ld = (l == 3) ? 3 : l + 1;
            const float gg = sg[l];
            const float ue = se[l] * su[l][i];
            const float4 v = *(const float4*)&sv[l][j4];
            float4 o;
            o.x = (1.0f - gg) * m[l].x + 0.5f * gg * (m[lu].x + m[ld].x) + ue * v.x;
            o.y = (1.0f - gg) * m[l].y + 0.5f * gg * (m[lu].y + m[ld].y) + ue * v.y;
            o.z = (1.0f - gg) * m[l].z + 0.5f * gg * (m[lu].z + m[ld].z) + ue * v.z;
            o.w = (1.0f - gg) * m[l].w + 0.5f * gg * (m[lu].w + m[ld].w) + ue * v.w;
            __stcs((float4*)(mout + (size_t)l * M_LVL_STRIDE + base), o);
        }
    }
}

// ---------------------------------------------------------------------------
template <typename F, typename... Args>
static void launch_pdl(F* fn, dim3 grid, dim3 block, size_t smem, Args... args)
{
    cudaLaunchConfig_t cfg = {};
    cfg.gridDim = grid;
    cfg.blockDim = block;
    cfg.dynamicSmemBytes = smem;
    cfg.stream = 0;
    cudaLaunchAttribute at[1];
    at[0].id = cudaLaunchAttributeProgrammaticStreamSerialization;
    at[0].val.programmaticStreamSerializationAllowed = 1;
    cfg.attrs = at;
    cfg.numAttrs = 1;
    cudaLaunchKernelEx(&cfg, fn, args...);
}

extern "C" void kernel_launch(void* const* d_in, const int* in_sizes, int n_in,
                              void* d_out, int out_size)
{
    const float* x       = (const float*)d_in[0];
    const float* c       = (const float*)d_in[1];
    const float* h       = (const float*)d_in[2];
    const float* M       = (const float*)d_in[3];
    const float* phi_w   = (const float*)d_in[4];
    const float* phi_b   = (const float*)d_in[5];
    const float* alpha_w = (const float*)d_in[6];
    const float* alpha_b = (const float*)d_in[7];
    const float* beta_w  = (const float*)d_in[8];
    const float* beta_b  = (const float*)d_in[9];
    const float* u_w     = (const float*)d_in[10];
    const float* u_b     = (const float*)d_in[11];
    const float* v_w     = (const float*)d_in[12];
    const float* v_b     = (const float*)d_in[13];
    const float* gamma_l = (const float*)d_in[14];
    const float* eta_l   = (const float*)d_in[15];

    float* out = (float*)d_out;

    // idempotent; first calls happen on the uncaptured correctness run
    cudaFuncSetAttribute(gate_gemm, cudaFuncAttributeMaxDynamicSharedMemorySize,
                         GATE_SMEM_BYTES);
    cudaFuncSetAttribute(uvxc_gemm, cudaFuncAttributeMaxDynamicSharedMemorySize,
                         UV_SMEM_BYTES);
    cudaFuncSetAttribute(uvh_gemm, cudaFuncAttributeMaxDynamicSharedMemorySize,
                         UV_SMEM_BYTES);

    // 1. gate GEMMs (trigger at top -> uv_xc fills freed SMs) -> g_gate_p
    gate_gemm<<<dim3(16, 4, 4), 128, GATE_SMEM_BYTES>>>(x, c, h,
                                                        phi_w, alpha_w, beta_w);
    // 2. uv_xc: h-independent 2/3 of u/v, overlaps gate tail -> g_uv_p[0..1]
    launch_pdl(uvxc_gemm, dim3(8, 4, 4), dim3(128), (size_t)UV_SMEM_BYTES,
               x, c, u_w, v_w);
    // 3. h_new (waits uv_xc => gate) -> out[0:H_SIZE]
    launch_pdl(hnew_kernel, dim3(H_SIZE4 / 256), dim3(256), (size_t)0,
               h, phi_b, alpha_b, beta_b, out);
    // 4. uv_h: h_new-dependent third of u/v -> g_uv_p[2]
    launch_pdl(uvh_gemm, dim3(8, 2, 4), dim3(128), (size_t)UV_SMEM_BYTES,
               out, u_w, v_w);
    // 5. fused 4-level M update (M prefetch before PDL wait) -> out[H_SIZE:]
    launch_pdl(m_update, dim3(8, 128), dim3(256), (size_t)0,
               M, gamma_l, eta_l, u_b, v_b, out);
}